// round 2
// baseline (speedup 1.0000x reference)
#include <cuda_runtime.h>
#include <cstdint>

#define BB 64
#define TT 72
#define SS 72
#define EE 128
#define HH 256
#define VV 32000
#define KK 512   // 2H

// ---------------- device scratch (static, allocation-free) ----------------
__device__ float g_c[BB * HH];                 // cell state
__device__ float g_stateT[2][KK][BB];          // transposed [h|ctx]: [k][b], double buffered
__device__ float g_WT[KK][VV];                 // transposed W_lin: [k][v]  (~65.5 MB)

// ---------------- f32x2 helpers (Blackwell packed fp32) ----------------
__device__ __forceinline__ unsigned long long pack2(float a, float b) {
    unsigned long long r;
    asm("mov.b64 %0, {%1,%2};" : "=l"(r) : "f"(a), "f"(b));
    return r;
}
__device__ __forceinline__ unsigned long long fma2(unsigned long long a,
                                                   unsigned long long b,
                                                   unsigned long long c) {
    unsigned long long d;
    asm("fma.rn.f32x2 %0, %1, %2, %3;" : "=l"(d) : "l"(a), "l"(b), "l"(c));
    return d;
}
__device__ __forceinline__ float2 unpack2(unsigned long long v) {
    float2 r;
    asm("mov.b64 {%0,%1}, %2;" : "=f"(r.x), "=f"(r.y) : "l"(v));
    return r;
}

__device__ __forceinline__ float sigf(float x) { return 1.0f / (1.0f + __expf(-x)); }

// ---------------- one-time transpose of W_lin ----------------
__global__ void transpose_W(const float* __restrict__ W) {
    __shared__ float tile[32][33];
    int v0 = blockIdx.x * 32, k0 = blockIdx.y * 32;
    int tx = threadIdx.x & 31, ty = threadIdx.x >> 5;  // 256 threads: 32x8
#pragma unroll
    for (int r = ty; r < 32; r += 8)
        tile[r][tx] = W[(size_t)(v0 + r) * KK + k0 + tx];
    __syncthreads();
#pragma unroll
    for (int r = ty; r < 32; r += 8)
        g_WT[k0 + r][v0 + tx] = tile[tx][r];
}

// ---------------- init h,c ----------------
__global__ void init_state(const float* __restrict__ h0, const float* __restrict__ c0) {
    int b = blockIdx.x, j = threadIdx.x;
    g_stateT[0][j][b] = h0[b * HH + j];
    g_c[b * HH + j]   = c0[b * HH + j];
}

// ---------------- LSTM gates + cell update ----------------
// grid (HH/32, BB/4) = (8,16), 128 threads.
// Block: 32 j-dims x 4 gates (=128 gate rows) x 4 batches.
__global__ void __launch_bounds__(128) lstm_step(
    int t, int rd, int wr,
    const int* __restrict__ target, const float* __restrict__ emb,
    const float* __restrict__ W_ih, const float* __restrict__ W_hh,
    const float* __restrict__ b_ih, const float* __restrict__ b_hh)
{
    __shared__ float sx[4][EE];
    __shared__ float sh[4][HH];
    __shared__ float sg[4][32][4];   // [gate][jl][bl]

    int tid = threadIdx.x;
    int j0 = blockIdx.x * 32;
    int b0 = blockIdx.y * 4;

    // load x = emb[token] for 4 batches (coalesced along E)
#pragma unroll
    for (int i = 0; i < 4; i++) {
        int idx = tid + i * 128;          // 512 floats
        int bl = idx >> 7, k = idx & 127;
        int tok = target[(b0 + bl) * TT + t];
        sx[bl][k] = emb[(size_t)tok * EE + k];
    }
    // load h_prev for 4 batches from transposed state
#pragma unroll
    for (int i = 0; i < 8; i++) {
        int idx = tid + i * 128;          // 1024 floats
        int bl = idx >> 8, j = idx & 255;
        sh[bl][j] = g_stateT[rd][j][b0 + bl];
    }
    __syncthreads();

    int gate = tid >> 5, jl = tid & 31;
    int row = gate * HH + j0 + jl;
    float bias = b_ih[row] + b_hh[row];
    float acc[4] = {bias, bias, bias, bias};

    const float4* wih = (const float4*)(W_ih + (size_t)row * EE);
#pragma unroll 8
    for (int kq = 0; kq < EE / 4; kq++) {
        float4 w = wih[kq];
#pragma unroll
        for (int bl = 0; bl < 4; bl++) {
            float4 x = *(const float4*)&sx[bl][kq * 4];
            acc[bl] = fmaf(w.x, x.x, acc[bl]);
            acc[bl] = fmaf(w.y, x.y, acc[bl]);
            acc[bl] = fmaf(w.z, x.z, acc[bl]);
            acc[bl] = fmaf(w.w, x.w, acc[bl]);
        }
    }
    const float4* whh = (const float4*)(W_hh + (size_t)row * HH);
#pragma unroll 8
    for (int kq = 0; kq < HH / 4; kq++) {
        float4 w = whh[kq];
#pragma unroll
        for (int bl = 0; bl < 4; bl++) {
            float4 h = *(const float4*)&sh[bl][kq * 4];
            acc[bl] = fmaf(w.x, h.x, acc[bl]);
            acc[bl] = fmaf(w.y, h.y, acc[bl]);
            acc[bl] = fmaf(w.z, h.z, acc[bl]);
            acc[bl] = fmaf(w.w, h.w, acc[bl]);
        }
    }
#pragma unroll
    for (int bl = 0; bl < 4; bl++) sg[gate][jl][bl] = acc[bl];
    __syncthreads();

    // cell + hidden update: 32 j x 4 b = 128 items = 128 threads
    {
        int jl2 = tid >> 2, bl2 = tid & 3;
        float gi = sg[0][jl2][bl2];
        float gf = sg[1][jl2][bl2];
        float gg = sg[2][jl2][bl2];
        float go = sg[3][jl2][bl2];
        int j = j0 + jl2, b = b0 + bl2;
        float c_old = g_c[b * HH + j];
        float c_new = sigf(gf) * c_old + sigf(gi) * tanhf(gg);
        float h_new = sigf(go) * tanhf(c_new);
        g_c[b * HH + j] = c_new;
        g_stateT[wr][j][b] = h_new;
    }
}

// ---------------- attention ----------------
// grid BB, 256 threads. Reads h_new (rows 0..255 of state), writes ctx (rows 256..511).
__global__ void __launch_bounds__(256) attn_step(
    int cur, const float* __restrict__ enc, const int* __restrict__ lens)
{
    __shared__ float shv[HH];
    __shared__ float sw[SS];
    __shared__ float sred;

    int b = blockIdx.x, tid = threadIdx.x;
    shv[tid] = g_stateT[cur][tid][b];
    __syncthreads();

    int len = lens[b];
    int w = tid >> 5, lane = tid & 31;
    for (int s = w; s < SS; s += 8) {
        const float* e = enc + ((size_t)b * SS + s) * HH;
        float acc = 0.f;
#pragma unroll
        for (int jj = lane; jj < HH; jj += 32) acc += shv[jj] * e[jj];
#pragma unroll
        for (int o = 16; o; o >>= 1) acc += __shfl_xor_sync(0xffffffffu, acc, o);
        if (lane == 0) sw[s] = (s < len) ? acc * 0.0625f : -1e30f;
    }
    __syncthreads();

    if (tid < 32) {
        float m = -1e30f;
        for (int s = tid; s < SS; s += 32) m = fmaxf(m, sw[s]);
#pragma unroll
        for (int o = 16; o; o >>= 1) m = fmaxf(m, __shfl_xor_sync(0xffffffffu, m, o));
        float sum = 0.f;
        for (int s = tid; s < SS; s += 32) {
            float e = __expf(sw[s] - m);
            sw[s] = e;
            sum += e;
        }
#pragma unroll
        for (int o = 16; o; o >>= 1) sum += __shfl_xor_sync(0xffffffffu, sum, o);
        if (tid == 0) sred = 1.0f / sum;
    }
    __syncthreads();

    float r = sred;
    float acc = 0.f;
    const float* e = enc + (size_t)b * SS * HH + tid;
#pragma unroll 8
    for (int s = 0; s < SS; s++) acc += sw[s] * e[(size_t)s * HH];
    g_stateT[cur][HH + tid][b] = acc * r;
}

// ---------------- output projection GEMM (f32x2) ----------------
// grid VV/256 = 125 blocks, 128 threads. Tile M=64 (all batches) x N=256.
// Thread tile 8(m) x 16(n) as 8 f32x2 pairs; FMA-bound (ratio 1.33 vs LDS).
__global__ void __launch_bounds__(128) gemm_step(
    int t, int cur, const float* __restrict__ b_lin, float* __restrict__ out)
{
    __shared__ float sA[32][64];    // [kk][m]
    __shared__ float sB[32][256];   // [kk][n]

    int tid = threadIdx.x;
    int n0g = blockIdx.x * 256;
    int mi = tid >> 4, ni = tid & 15;
    int m0 = mi * 8, nb = ni * 16;

    unsigned long long acc[8][8];
#pragma unroll
    for (int m = 0; m < 8; m++)
#pragma unroll
        for (int p = 0; p < 8; p++) acc[m][p] = 0ULL;

    for (int ko = 0; ko < 16; ko++) {
        int k0 = ko * 32;
        // fill sA: 2048 floats = 512 float4
#pragma unroll
        for (int i = 0; i < 4; i++) {
            int idx = tid + i * 128;
            int kk = idx >> 4, m4 = idx & 15;
            *(float4*)&sA[kk][m4 * 4] =
                *(const float4*)&g_stateT[cur][k0 + kk][m4 * 4];
        }
        // fill sB: 8192 floats = 2048 float4 (coalesced rows of g_WT)
#pragma unroll
        for (int i = 0; i < 16; i++) {
            int idx = tid + i * 128;
            int kk = idx >> 6, v4 = idx & 63;
            *(float4*)&sB[kk][v4 * 4] =
                *(const float4*)&g_WT[k0 + kk][n0g + v4 * 4];
        }
        __syncthreads();

#pragma unroll
        for (int kk = 0; kk < 32; kk++) {
            float4 a0 = *(const float4*)&sA[kk][m0];
            float4 a1 = *(const float4*)&sA[kk][m0 + 4];
            const ulonglong2* bp = (const ulonglong2*)&sB[kk][nb];
            ulonglong2 q0 = bp[0], q1 = bp[1], q2 = bp[2], q3 = bp[3];
            unsigned long long bq[8] = {q0.x, q0.y, q1.x, q1.y,
                                        q2.x, q2.y, q3.x, q3.y};
            float av[8] = {a0.x, a0.y, a0.z, a0.w, a1.x, a1.y, a1.z, a1.w};
#pragma unroll
            for (int m = 0; m < 8; m++) {
                unsigned long long a2 = pack2(av[m], av[m]);
#pragma unroll
                for (int p = 0; p < 8; p++) acc[m][p] = fma2(a2, bq[p], acc[m][p]);
            }
        }
        __syncthreads();
    }

    // epilogue: add bias, store to out[b][t][v]
#pragma unroll
    for (int m = 0; m < 8; m++) {
        int b = m0 + m;
        float* orow = out + ((size_t)(b * TT + t)) * VV + n0g + nb;
#pragma unroll
        for (int p = 0; p < 8; p++) {
            float2 v = unpack2(acc[m][p]);
            float2 bi = *(const float2*)&b_lin[n0g + nb + p * 2];
            float2 o;
            o.x = v.x + bi.x;
            o.y = v.y + bi.y;
            *(float2*)&orow[p * 2] = o;
        }
    }
}

// ---------------- launch ----------------
extern "C" void kernel_launch(void* const* d_in, const int* in_sizes, int n_in,
                              void* d_out, int out_size)
{
    const int*   target = (const int*)d_in[0];
    const float* enc    = (const float*)d_in[1];
    const int*   lens   = (const int*)d_in[2];
    const float* h0     = (const float*)d_in[3];
    const float* c0     = (const float*)d_in[4];
    const float* emb    = (const float*)d_in[5];
    const float* W_ih   = (const float*)d_in[6];
    const float* W_hh   = (const float*)d_in[7];
    const float* b_ih   = (const float*)d_in[8];
    const float* b_hh   = (const float*)d_in[9];
    const float* W_lin  = (const float*)d_in[10];
    const float* b_lin  = (const float*)d_in[11];
    float* out = (float*)d_out;

    transpose_W<<<dim3(VV / 32, KK / 32), 256>>>(W_lin);
    init_state<<<BB, HH>>>(h0, c0);

    for (int t = 0; t < TT; t++) {
        int rd = t & 1, wr = rd ^ 1;
        lstm_step<<<dim3(HH / 32, BB / 4), 128>>>(t, rd, wr, target, emb,
                                                  W_ih, W_hh, b_ih, b_hh);
        attn_step<<<BB, 256>>>(wr, enc, lens);
        gemm_step<<<VV / 256, 128>>>(t, wr, b_lin, out);
    }
}

// round 3
// speedup vs baseline: 1.6262x; 1.6262x over previous
#include <cuda_runtime.h>
#include <cstdint>

#define BB 64
#define TT 72
#define SS 72
#define EE 128
#define HH 256
#define VV 32000
#define KK 512   // 2H
#define KC 16    // gemm K-chunk
#define NCH (KK / KC)

typedef unsigned long long ull;

// ---------------- device scratch (static, allocation-free) ----------------
__device__ float g_c[BB * HH];            // cell state
__device__ float g_h[2][BB][HH];          // h in natural layout (coalesced reads)
__device__ float g_stateT[2][KK][BB];     // transposed [h|ctx]: [k][b]
__device__ float g_WT[KK][VV];            // transposed W_lin (~65.5 MB)

// ---------------- f32x2 / async helpers ----------------
__device__ __forceinline__ ull pack2(float a, float b) {
    ull r;
    asm("mov.b64 %0, {%1,%2};" : "=l"(r) : "f"(a), "f"(b));
    return r;
}
__device__ __forceinline__ ull fma2(ull a, ull b, ull c) {
    ull d;
    asm("fma.rn.f32x2 %0, %1, %2, %3;" : "=l"(d) : "l"(a), "l"(b), "l"(c));
    return d;
}
__device__ __forceinline__ float2 unpack2(ull v) {
    float2 r;
    asm("mov.b64 {%0,%1}, %2;" : "=f"(r.x), "=f"(r.y) : "l"(v));
    return r;
}
__device__ __forceinline__ void cp16(void* dst_smem, const void* src) {
    unsigned sa = (unsigned)__cvta_generic_to_shared(dst_smem);
    asm volatile("cp.async.cg.shared.global [%0], [%1], 16;" :: "r"(sa), "l"(src));
}
#define CP_COMMIT() asm volatile("cp.async.commit_group;")
#define CP_WAIT1()  asm volatile("cp.async.wait_group 1;")

__device__ __forceinline__ float sigf(float x) { return 1.0f / (1.0f + __expf(-x)); }

// ---------------- one-time transpose of W_lin ----------------
__global__ void transpose_W(const float* __restrict__ W) {
    __shared__ float tile[32][33];
    int v0 = blockIdx.x * 32, k0 = blockIdx.y * 32;
    int tx = threadIdx.x & 31, ty = threadIdx.x >> 5;
#pragma unroll
    for (int r = ty; r < 32; r += 8)
        tile[r][tx] = W[(size_t)(v0 + r) * KK + k0 + tx];
    __syncthreads();
#pragma unroll
    for (int r = ty; r < 32; r += 8)
        g_WT[k0 + r][v0 + tx] = tile[tx][r];
}

// ---------------- init h,c ----------------
__global__ void init_state(const float* __restrict__ h0, const float* __restrict__ c0) {
    int b = blockIdx.x, j = threadIdx.x;
    float h = h0[b * HH + j];
    g_h[0][b][j]      = h;
    g_stateT[0][j][b] = h;
    g_c[b * HH + j]   = c0[b * HH + j];
}

// ---------------- LSTM gates + cell update ----------------
// grid (HH/32, BB/4) = (8,16), 128 threads.
__global__ void __launch_bounds__(128) lstm_step(
    int t, int rd, int wr,
    const int* __restrict__ target, const float* __restrict__ emb,
    const float* __restrict__ W_ih, const float* __restrict__ W_hh,
    const float* __restrict__ b_ih, const float* __restrict__ b_hh)
{
    __shared__ float sx[4][EE];
    __shared__ float sh[4][HH];
    __shared__ float sg[4][32][4];

    int tid = threadIdx.x;
    int j0 = blockIdx.x * 32;
    int b0 = blockIdx.y * 4;

#pragma unroll
    for (int i = 0; i < 4; i++) {
        int idx = tid + i * 128;
        int bl = idx >> 7, k = idx & 127;
        int tok = target[(b0 + bl) * TT + t];
        sx[bl][k] = emb[(size_t)tok * EE + k];
    }
#pragma unroll
    for (int i = 0; i < 8; i++) {
        int idx = tid + i * 128;
        int bl = idx >> 8, j = idx & 255;
        sh[bl][j] = g_h[rd][b0 + bl][j];
    }
    __syncthreads();

    int gate = tid >> 5, jl = tid & 31;
    int row = gate * HH + j0 + jl;
    float bias = b_ih[row] + b_hh[row];
    float acc[4] = {bias, bias, bias, bias};

    const float4* wih = (const float4*)(W_ih + (size_t)row * EE);
#pragma unroll 8
    for (int kq = 0; kq < EE / 4; kq++) {
        float4 w = wih[kq];
#pragma unroll
        for (int bl = 0; bl < 4; bl++) {
            float4 x = *(const float4*)&sx[bl][kq * 4];
            acc[bl] = fmaf(w.x, x.x, acc[bl]);
            acc[bl] = fmaf(w.y, x.y, acc[bl]);
            acc[bl] = fmaf(w.z, x.z, acc[bl]);
            acc[bl] = fmaf(w.w, x.w, acc[bl]);
        }
    }
    const float4* whh = (const float4*)(W_hh + (size_t)row * HH);
#pragma unroll 8
    for (int kq = 0; kq < HH / 4; kq++) {
        float4 w = whh[kq];
#pragma unroll
        for (int bl = 0; bl < 4; bl++) {
            float4 h = *(const float4*)&sh[bl][kq * 4];
            acc[bl] = fmaf(w.x, h.x, acc[bl]);
            acc[bl] = fmaf(w.y, h.y, acc[bl]);
            acc[bl] = fmaf(w.z, h.z, acc[bl]);
            acc[bl] = fmaf(w.w, h.w, acc[bl]);
        }
    }
#pragma unroll
    for (int bl = 0; bl < 4; bl++) sg[gate][jl][bl] = acc[bl];
    __syncthreads();

    {
        int jl2 = tid >> 2, bl2 = tid & 3;
        float gi = sg[0][jl2][bl2];
        float gf = sg[1][jl2][bl2];
        float gg = sg[2][jl2][bl2];
        float go = sg[3][jl2][bl2];
        int j = j0 + jl2, b = b0 + bl2;
        float c_old = g_c[b * HH + j];
        float c_new = sigf(gf) * c_old + sigf(gi) * tanhf(gg);
        float h_new = sigf(go) * tanhf(c_new);
        g_c[b * HH + j] = c_new;
        g_h[wr][b][j]      = h_new;
        g_stateT[wr][j][b] = h_new;
    }
}

// ---------------- attention (smem-resident enc tile) ----------------
// grid BB, 512 threads, ~76 KB dynamic smem.
__global__ void __launch_bounds__(512) attn_step(
    int cur, const float* __restrict__ enc, const int* __restrict__ lens)
{
    extern __shared__ float sm[];
    float (*se)[HH] = (float(*)[HH])sm;       // [72][256]
    float* sw   = sm + SS * HH;               // [72]
    float* part = sw + SS;                    // [2][256]
    __shared__ float shv[HH];
    __shared__ float sred;

    int b = blockIdx.x, tid = threadIdx.x;

    // load enc tile: 4608 float4 with high MLP
    const float4* esrc = (const float4*)(enc + (size_t)b * SS * HH);
    float4* sdst = (float4*)se;
#pragma unroll
    for (int i = 0; i < 9; i++) sdst[tid + i * 512] = esrc[tid + i * 512];
    if (tid < HH) shv[tid] = g_h[cur][b][tid];
    __syncthreads();

    int len = lens[b];
    int w = tid >> 5, lane = tid & 31;
    for (int s = w; s < SS; s += 16) {
        float acc = 0.f;
#pragma unroll
        for (int j = lane; j < HH; j += 32) acc += shv[j] * se[s][j];
#pragma unroll
        for (int o = 16; o; o >>= 1) acc += __shfl_xor_sync(0xffffffffu, acc, o);
        if (lane == 0) sw[s] = (s < len) ? acc * 0.0625f : -1e30f;
    }
    __syncthreads();

    if (tid < 32) {
        float m = -1e30f;
        for (int s = tid; s < SS; s += 32) m = fmaxf(m, sw[s]);
#pragma unroll
        for (int o = 16; o; o >>= 1) m = fmaxf(m, __shfl_xor_sync(0xffffffffu, m, o));
        float sum = 0.f;
        for (int s = tid; s < SS; s += 32) {
            float e = __expf(sw[s] - m);
            sw[s] = e;
            sum += e;
        }
#pragma unroll
        for (int o = 16; o; o >>= 1) sum += __shfl_xor_sync(0xffffffffu, sum, o);
        if (tid == 0) sred = 1.0f / sum;
    }
    __syncthreads();

    // ctx: split S into two halves across 512 threads
    {
        int j = tid & 255, half = tid >> 8;
        int s0 = half * 36;
        float acc = 0.f;
#pragma unroll
        for (int s = 0; s < 36; s++) acc += sw[s0 + s] * se[s0 + s][j];
        part[half * 256 + j] = acc;
    }
    __syncthreads();
    if (tid < 256)
        g_stateT[cur][HH + tid][b] = (part[tid] + part[256 + tid]) * sred;
}

// ---------------- output projection GEMM (f32x2, cp.async double-buffer) ----------------
// grid VV/256 = 125 blocks, 256 threads. Block tile 64M x 256N.
// Thread tile 8m x 8n (two 4-wide groups at ni*4 and 128+ni*4).
__global__ void __launch_bounds__(256) gemm_step(
    int t, int cur, const float* __restrict__ b_lin, float* __restrict__ out)
{
    __shared__ float sA[2][KC][64];     // 8 KB
    __shared__ float sB[2][KC][256];    // 32 KB

    int tid = threadIdx.x;
    int n0g = blockIdx.x * 256;
    int mi = tid >> 5, ni = tid & 31;
    int m0 = mi * 8;

    ull acc[8][4];
#pragma unroll
    for (int m = 0; m < 8; m++)
#pragma unroll
        for (int p = 0; p < 4; p++) acc[m][p] = 0ULL;

    // prefetch indices
    int akk = tid >> 4, am4 = tid & 15;

    // prefetch chunk 0 -> buf 0
    cp16(&sA[0][akk][am4 * 4], &g_stateT[cur][akk][am4 * 4]);
#pragma unroll
    for (int i = 0; i < 4; i++) {
        int idx = tid + i * 256;
        int kk = idx >> 6, v4 = idx & 63;
        cp16(&sB[0][kk][v4 * 4], &g_WT[kk][n0g + v4 * 4]);
    }
    CP_COMMIT();

    for (int ko = 0; ko < NCH; ko++) {
        int buf = ko & 1;
        __syncthreads();   // everyone done computing buf^1 before we overwrite it
        if (ko + 1 < NCH) {
            int k0 = (ko + 1) * KC;
            cp16(&sA[buf ^ 1][akk][am4 * 4], &g_stateT[cur][k0 + akk][am4 * 4]);
#pragma unroll
            for (int i = 0; i < 4; i++) {
                int idx = tid + i * 256;
                int kk = idx >> 6, v4 = idx & 63;
                cp16(&sB[buf ^ 1][kk][v4 * 4], &g_WT[k0 + kk][n0g + v4 * 4]);
            }
        }
        CP_COMMIT();
        CP_WAIT1();        // chunk ko complete (this thread)
        __syncthreads();   // chunk ko complete (all threads)

        const float (*pA)[64]  = sA[buf];
        const float (*pB)[256] = sB[buf];
#pragma unroll
        for (int kk = 0; kk < KC; kk++) {
            float4 a0 = *(const float4*)&pA[kk][m0];
            float4 a1 = *(const float4*)&pA[kk][m0 + 4];
            float4 b0 = *(const float4*)&pB[kk][ni * 4];
            float4 b1 = *(const float4*)&pB[kk][128 + ni * 4];
            ull bq0 = pack2(b0.x, b0.y), bq1 = pack2(b0.z, b0.w);
            ull bq2 = pack2(b1.x, b1.y), bq3 = pack2(b1.z, b1.w);
            float av[8] = {a0.x, a0.y, a0.z, a0.w, a1.x, a1.y, a1.z, a1.w};
#pragma unroll
            for (int m = 0; m < 8; m++) {
                ull a2 = pack2(av[m], av[m]);
                acc[m][0] = fma2(a2, bq0, acc[m][0]);
                acc[m][1] = fma2(a2, bq1, acc[m][1]);
                acc[m][2] = fma2(a2, bq2, acc[m][2]);
                acc[m][3] = fma2(a2, bq3, acc[m][3]);
            }
        }
    }

    // epilogue
    float4 bi0 = *(const float4*)&b_lin[n0g + ni * 4];
    float4 bi1 = *(const float4*)&b_lin[n0g + 128 + ni * 4];
#pragma unroll
    for (int m = 0; m < 8; m++) {
        int b = m0 + m;
        float* orow = out + ((size_t)(b * TT + t)) * VV + n0g;
        float2 v0 = unpack2(acc[m][0]), v1 = unpack2(acc[m][1]);
        float2 v2 = unpack2(acc[m][2]), v3 = unpack2(acc[m][3]);
        float4 o0 = {v0.x + bi0.x, v0.y + bi0.y, v1.x + bi0.z, v1.y + bi0.w};
        float4 o1 = {v2.x + bi1.x, v2.y + bi1.y, v3.x + bi1.z, v3.y + bi1.w};
        *(float4*)&orow[ni * 4]       = o0;
        *(float4*)&orow[128 + ni * 4] = o1;
    }
}

// ---------------- launch ----------------
extern "C" void kernel_launch(void* const* d_in, const int* in_sizes, int n_in,
                              void* d_out, int out_size)
{
    const int*   target = (const int*)d_in[0];
    const float* enc    = (const float*)d_in[1];
    const int*   lens   = (const int*)d_in[2];
    const float* h0     = (const float*)d_in[3];
    const float* c0     = (const float*)d_in[4];
    const float* emb    = (const float*)d_in[5];
    const float* W_ih   = (const float*)d_in[6];
    const float* W_hh   = (const float*)d_in[7];
    const float* b_ih   = (const float*)d_in[8];
    const float* b_hh   = (const float*)d_in[9];
    const float* W_lin  = (const float*)d_in[10];
    const float* b_lin  = (const float*)d_in[11];
    float* out = (float*)d_out;

    const int attn_smem = (SS * HH + SS + 2 * HH) * (int)sizeof(float);
    cudaFuncSetAttribute(attn_step, cudaFuncAttributeMaxDynamicSharedMemorySize,
                         attn_smem);

    transpose_W<<<dim3(VV / 32, KK / 32), 256>>>(W_lin);
    init_state<<<BB, HH>>>(h0, c0);

    for (int t = 0; t < TT; t++) {
        int rd = t & 1, wr = rd ^ 1;
        lstm_step<<<dim3(HH / 32, BB / 4), 128>>>(t, rd, wr, target, emb,
                                                  W_ih, W_hh, b_ih, b_hh);
        attn_step<<<BB, 512, attn_smem>>>(wr, enc, lens);
        gemm_step<<<VV / 256, 256>>>(t, wr, b_lin, out);
    }
}

// round 6
// speedup vs baseline: 2.4995x; 1.5371x over previous
#include <cuda_runtime.h>
#include <cuda_bf16.h>
#include <cstdint>

#define BB 64
#define TT 72
#define SS 72
#define EE 128
#define HH 256
#define VV 32000
#define KK 512
#define NTILE 256
#define KCH 64
#define NCH (KK / KCH)   // 8

typedef unsigned long long ull;

// ---------------- device scratch (static, allocation-free) ----------------
__device__ float g_c[BB * HH];
__device__ float g_h[2][BB][HH];                 // natural layout h
__device__ __nv_bfloat16 g_Ah[2][BB][KK];        // state hi
__device__ __nv_bfloat16 g_Al[2][BB][KK];        // state lo
__device__ __nv_bfloat16 g_Wh[(size_t)VV * KK];  // W_lin hi (32.8 MB)
__device__ __nv_bfloat16 g_Wl[(size_t)VV * KK];  // W_lin lo (32.8 MB)

// ---------------- PTX helpers ----------------
__device__ __forceinline__ uint32_t smem_u32(const void* p) {
    uint32_t a;
    asm("{ .reg .u64 t; cvta.to.shared.u64 t, %1; cvt.u32.u64 %0, t; }"
        : "=r"(a) : "l"(p));
    return a;
}
__device__ __forceinline__ void cp16(uint32_t dst_smem, const void* src) {
    asm volatile("cp.async.cg.shared.global [%0], [%1], 16;"
                 :: "r"(dst_smem), "l"(src));
}
#define CP_COMMIT() asm volatile("cp.async.commit_group;")
#define CP_WAIT1()  asm volatile("cp.async.wait_group 1;" ::: "memory")
#define CP_WAIT0()  asm volatile("cp.async.wait_group 0;" ::: "memory")

__device__ __forceinline__ void ldm_x4(uint32_t a, uint32_t* r) {
    asm volatile("ldmatrix.sync.aligned.m8n8.x4.shared.b16 {%0,%1,%2,%3}, [%4];"
                 : "=r"(r[0]), "=r"(r[1]), "=r"(r[2]), "=r"(r[3]) : "r"(a));
}
__device__ __forceinline__ void ldm_x2(uint32_t a, uint32_t* r) {
    asm volatile("ldmatrix.sync.aligned.m8n8.x2.shared.b16 {%0,%1}, [%2];"
                 : "=r"(r[0]), "=r"(r[1]) : "r"(a));
}
__device__ __forceinline__ void mma_bf16(float* c, const uint32_t* a,
                                         const uint32_t* b) {
    asm volatile(
        "mma.sync.aligned.m16n8k16.row.col.f32.bf16.bf16.f32 "
        "{%0,%1,%2,%3}, {%4,%5,%6,%7}, {%8,%9}, {%0,%1,%2,%3};"
        : "+f"(c[0]), "+f"(c[1]), "+f"(c[2]), "+f"(c[3])
        : "r"(a[0]), "r"(a[1]), "r"(a[2]), "r"(a[3]), "r"(b[0]), "r"(b[1]));
}

__device__ __forceinline__ uint32_t sw128(uint32_t off) {
    return off ^ ((off >> 3) & 0x70);
}
__device__ __forceinline__ float sigf(float x) { return 1.0f / (1.0f + __expf(-x)); }

// ---------------- one-time prep ----------------
__global__ void convert_W(const float* __restrict__ W) {
    size_t i = (size_t)blockIdx.x * blockDim.x + threadIdx.x;
    float w = W[i];
    __nv_bfloat16 hi = __float2bfloat16(w);
    g_Wh[i] = hi;
    g_Wl[i] = __float2bfloat16(w - __bfloat162float(hi));
}
__global__ void init_state(const float* __restrict__ h0, const float* __restrict__ c0) {
    int b = blockIdx.x, j = threadIdx.x;
    g_h[0][b][j]    = h0[b * HH + j];
    g_c[b * HH + j] = c0[b * HH + j];
}

// ---------------- LSTM step ----------------
__global__ void __launch_bounds__(128) lstm_step(
    int t, int rd, int wr,
    const int* __restrict__ target, const float* __restrict__ emb,
    const float* __restrict__ W_ih, const float* __restrict__ W_hh,
    const float* __restrict__ b_ih, const float* __restrict__ b_hh)
{
    __shared__ float sx[4][EE];
    __shared__ float sh[4][HH];
    __shared__ float sg[4][32][4];

    int tid = threadIdx.x;
    int j0 = blockIdx.x * 32;
    int b0 = blockIdx.y * 4;

#pragma unroll
    for (int i = 0; i < 4; i++) {
        int idx = tid + i * 128;
        int bl = idx >> 7, k = idx & 127;
        int tok = target[(b0 + bl) * TT + t];
        sx[bl][k] = emb[(size_t)tok * EE + k];
    }
#pragma unroll
    for (int i = 0; i < 8; i++) {
        int idx = tid + i * 128;
        int bl = idx >> 8, j = idx & 255;
        sh[bl][j] = g_h[rd][b0 + bl][j];
    }
    __syncthreads();

    int gate = tid >> 5, jl = tid & 31;
    int row = gate * HH + j0 + jl;
    float bias = b_ih[row] + b_hh[row];
    float acc[4] = {bias, bias, bias, bias};

    const float4* wih = (const float4*)(W_ih + (size_t)row * EE);
#pragma unroll 8
    for (int kq = 0; kq < EE / 4; kq++) {
        float4 w = wih[kq];
#pragma unroll
        for (int bl = 0; bl < 4; bl++) {
            float4 x = *(const float4*)&sx[bl][kq * 4];
            acc[bl] = fmaf(w.x, x.x, acc[bl]);
            acc[bl] = fmaf(w.y, x.y, acc[bl]);
            acc[bl] = fmaf(w.z, x.z, acc[bl]);
            acc[bl] = fmaf(w.w, x.w, acc[bl]);
        }
    }
    const float4* whh = (const float4*)(W_hh + (size_t)row * HH);
#pragma unroll 8
    for (int kq = 0; kq < HH / 4; kq++) {
        float4 w = whh[kq];
#pragma unroll
        for (int bl = 0; bl < 4; bl++) {
            float4 h = *(const float4*)&sh[bl][kq * 4];
            acc[bl] = fmaf(w.x, h.x, acc[bl]);
            acc[bl] = fmaf(w.y, h.y, acc[bl]);
            acc[bl] = fmaf(w.z, h.z, acc[bl]);
            acc[bl] = fmaf(w.w, h.w, acc[bl]);
        }
    }
#pragma unroll
    for (int bl = 0; bl < 4; bl++) sg[gate][jl][bl] = acc[bl];
    __syncthreads();

    {
        int jl2 = tid >> 2, bl2 = tid & 3;
        float gi = sg[0][jl2][bl2];
        float gf = sg[1][jl2][bl2];
        float gg = sg[2][jl2][bl2];
        float go = sg[3][jl2][bl2];
        int j = j0 + jl2, b = b0 + bl2;
        float c_old = g_c[b * HH + j];
        float c_new = sigf(gf) * c_old + sigf(gi) * tanhf(gg);
        float h_new = sigf(go) * tanhf(c_new);
        g_c[b * HH + j] = c_new;
        g_h[wr][b][j]   = h_new;
        __nv_bfloat16 hi = __float2bfloat16(h_new);
        g_Ah[wr][b][j] = hi;
        g_Al[wr][b][j] = __float2bfloat16(h_new - __bfloat162float(hi));
    }
}

// ---------------- attention ----------------
__global__ void __launch_bounds__(512) attn_step(
    int cur, const float* __restrict__ enc, const int* __restrict__ lens)
{
    extern __shared__ float sm[];
    float (*se)[HH] = (float(*)[HH])sm;       // [72][256]
    float* sw   = sm + SS * HH;               // [72]
    float* part = sw + SS;                    // [2][256]
    __shared__ float shv[HH];
    __shared__ float sred;

    int b = blockIdx.x, tid = threadIdx.x;

    const float4* esrc = (const float4*)(enc + (size_t)b * SS * HH);
    float4* sdst = (float4*)se;
#pragma unroll
    for (int i = 0; i < 9; i++) sdst[tid + i * 512] = esrc[tid + i * 512];
    if (tid < HH) shv[tid] = g_h[cur][b][tid];
    __syncthreads();

    int len = lens[b];
    int w = tid >> 5, lane = tid & 31;
    for (int s = w; s < SS; s += 16) {
        float acc = 0.f;
#pragma unroll
        for (int j = lane; j < HH; j += 32) acc += shv[j] * se[s][j];
#pragma unroll
        for (int o = 16; o; o >>= 1) acc += __shfl_xor_sync(0xffffffffu, acc, o);
        if (lane == 0) sw[s] = (s < len) ? acc * 0.0625f : -1e30f;
    }
    __syncthreads();

    if (tid < 32) {
        float m = -1e30f;
        for (int s = tid; s < SS; s += 32) m = fmaxf(m, sw[s]);
#pragma unroll
        for (int o = 16; o; o >>= 1) m = fmaxf(m, __shfl_xor_sync(0xffffffffu, m, o));
        float sum = 0.f;
        for (int s = tid; s < SS; s += 32) {
            float e = __expf(sw[s] - m);
            sw[s] = e;
            sum += e;
        }
#pragma unroll
        for (int o = 16; o; o >>= 1) sum += __shfl_xor_sync(0xffffffffu, sum, o);
        if (tid == 0) sred = 1.0f / sum;
    }
    __syncthreads();

    {
        int j = tid & 255, half = tid >> 8;
        int s0 = half * 36;
        float acc = 0.f;
#pragma unroll
        for (int s = 0; s < 36; s++) acc += sw[s0 + s] * se[s0 + s][j];
        part[half * 256 + j] = acc;
    }
    __syncthreads();
    if (tid < 256) {
        float ctx = (part[tid] + part[256 + tid]) * sred;
        __nv_bfloat16 hi = __float2bfloat16(ctx);
        g_Ah[cur][b][HH + tid] = hi;
        g_Al[cur][b][HH + tid] = __float2bfloat16(ctx - __bfloat162float(hi));
    }
}

// ---------------- output projection: HMMA bf16-split GEMM ----------------
// 125 CTAs x 256 threads (8 warps). CTA tile 64M x 256N; warp = 64M x 32N.
// K-chunks of 64 bf16 (128B rows, SW128). cp.async double buffer, 160 KB smem.
#define OFF_AL 8192
#define OFF_BH 16384
#define OFF_BL 49152
#define STAGE  81920

__global__ void __launch_bounds__(256) gemm_step(
    int t, int cur, const float* __restrict__ b_lin, float* __restrict__ out)
{
    extern __shared__ __align__(1024) char smc[];
    uint32_t sb = smem_u32(smc);
    int tid = threadIdx.x, wid = tid >> 5, lane = tid & 31;
    int n0g = blockIdx.x * NTILE;

    // ---- chunk loader ----
    auto load_chunk = [&](int ko, int s) {
        int k0 = ko * KCH;
        uint32_t base = sb + s * STAGE;
#pragma unroll
        for (int i = 0; i < 2; i++) {                  // A: 64 rows x 8 segs
            int idx = tid + i * 256;
            int r = idx >> 3, sg = idx & 7;
            uint32_t o = sw128((uint32_t)(r * 128 + sg * 16));
            cp16(base + o,          &g_Ah[cur][r][k0 + sg * 8]);
            cp16(base + OFF_AL + o, &g_Al[cur][r][k0 + sg * 8]);
        }
#pragma unroll
        for (int i = 0; i < 8; i++) {                  // B: 256 rows x 8 segs
            int idx = tid + i * 256;
            int r = idx >> 3, sg = idx & 7;
            uint32_t o = sw128((uint32_t)(r * 128 + sg * 16));
            size_t gi = (size_t)(n0g + r) * KK + k0 + sg * 8;
            cp16(base + OFF_BH + o, &g_Wh[gi]);
            cp16(base + OFF_BL + o, &g_Wl[gi]);
        }
        CP_COMMIT();
    };

    float acc[4][4][4];
#pragma unroll
    for (int mt = 0; mt < 4; mt++)
#pragma unroll
        for (int nt = 0; nt < 4; nt++)
#pragma unroll
            for (int r = 0; r < 4; r++) acc[mt][nt][r] = 0.f;

    // per-lane ldmatrix address components
    int l15 = lane & 15;
    int aKhalf = (lane >> 4) * 16;      // A: lanes 16-31 take k+8 (16 bytes)
    int bKhalf = ((lane >> 3) & 1) * 16; // B: lanes 8-15 take k+8
    int bRow = lane & 7;

    load_chunk(0, 0);

    for (int ko = 0; ko < NCH; ko++) {
        int buf = ko & 1;
        if (ko + 1 < NCH) {
            load_chunk(ko + 1, buf ^ 1);
            CP_WAIT1();
        } else {
            CP_WAIT0();
        }
        __syncthreads();   // chunk ko visible to all

        uint32_t base = sb + buf * STAGE;
#pragma unroll
        for (int ks = 0; ks < 4; ks++) {
            uint32_t ah[4][4], al[4][4], bh[4][2], blr[4][2];
#pragma unroll
            for (int mt = 0; mt < 4; mt++) {
                uint32_t off = sw128((uint32_t)((mt * 16 + l15) * 128 +
                                                ks * 32 + aKhalf));
                ldm_x4(base + off, ah[mt]);
                ldm_x4(base + OFF_AL + off, al[mt]);
            }
#pragma unroll
            for (int nt = 0; nt < 4; nt++) {
                uint32_t off = sw128((uint32_t)((wid * 32 + nt * 8 + bRow) * 128 +
                                                ks * 32 + bKhalf));
                ldm_x2(base + OFF_BH + off, bh[nt]);
                ldm_x2(base + OFF_BL + off, blr[nt]);
            }
#pragma unroll
            for (int mt = 0; mt < 4; mt++)
#pragma unroll
                for (int nt = 0; nt < 4; nt++) {
                    mma_bf16(acc[mt][nt], ah[mt], bh[nt]);
                    mma_bf16(acc[mt][nt], ah[mt], blr[nt]);
                    mma_bf16(acc[mt][nt], al[mt], bh[nt]);
                }
        }
        __syncthreads();   // done reading buf before it is overwritten
    }

    // ---- epilogue: fragment regs -> gmem (float2 stores) ----
    int qr = lane >> 2, qc = lane & 3;
#pragma unroll
    for (int nt = 0; nt < 4; nt++) {
        int v = n0g + wid * 32 + nt * 8 + qc * 2;
        float2 bi = *(const float2*)&b_lin[v];
#pragma unroll
        for (int mt = 0; mt < 4; mt++) {
            int bA = mt * 16 + qr;
            int bBt = bA + 8;
            float2 lo = {acc[mt][nt][0] + bi.x, acc[mt][nt][1] + bi.y};
            float2 hi = {acc[mt][nt][2] + bi.x, acc[mt][nt][3] + bi.y};
            *(float2*)&out[((size_t)(bA * TT + t)) * VV + v]  = lo;
            *(float2*)&out[((size_t)(bBt * TT + t)) * VV + v] = hi;
        }
    }
}

// ---------------- launch ----------------
extern "C" void kernel_launch(void* const* d_in, const int* in_sizes, int n_in,
                              void* d_out, int out_size)
{
    const int*   target = (const int*)d_in[0];
    const float* enc    = (const float*)d_in[1];
    const int*   lens   = (const int*)d_in[2];
    const float* h0     = (const float*)d_in[3];
    const float* c0     = (const float*)d_in[4];
    const float* emb    = (const float*)d_in[5];
    const float* W_ih   = (const float*)d_in[6];
    const float* W_hh   = (const float*)d_in[7];
    const float* b_ih   = (const float*)d_in[8];
    const float* b_hh   = (const float*)d_in[9];
    const float* W_lin  = (const float*)d_in[10];
    const float* b_lin  = (const float*)d_in[11];
    float* out = (float*)d_out;

    const int attn_smem = (SS * HH + SS + 2 * HH) * (int)sizeof(float);
    cudaFuncSetAttribute(attn_step, cudaFuncAttributeMaxDynamicSharedMemorySize,
                         attn_smem);
    const int gemm_smem = 2 * STAGE;   // 160 KB
    cudaFuncSetAttribute(gemm_step, cudaFuncAttributeMaxDynamicSharedMemorySize,
                         gemm_smem);

    convert_W<<<VV * KK / 512, 512>>>(W_lin);
    init_state<<<BB, HH>>>(h0, c0);

    for (int t = 0; t < TT; t++) {
        int rd = t & 1, wr = rd ^ 1;
        lstm_step<<<dim3(HH / 32, BB / 4), 128>>>(t, rd, wr, target, emb,
                                                  W_ih, W_hh, b_ih, b_hh);
        attn_step<<<BB, 512, attn_smem>>>(wr, enc, lens);
        gemm_step<<<VV / NTILE, 256, gemm_smem>>>(t, wr, b_lin, out);
    }
}